// round 3
// baseline (speedup 1.0000x reference)
#include <cuda_runtime.h>
#include <math.h>

// B = H = IN = 256, c = 1. Dead code (Wh*/Uh*, r_point_h) skipped.

#define NB 256
#define MAXN 0.996f          // (1 - 4e-3)/sqrt(c)
#define EPSN 1e-15f
#define CLIPV 0.9999999f     // 1 - 1e-7 in f32

// ---------------- scratch ---------------------------------------------------
__device__ float g_w[4][NB * NB];     // w = sinh(mlr logits) per fc, [b][cl]
__device__ float g_scale[4][NB];      // sqrt(row-sumsq of w)+1

// ---------------- fast math helpers -----------------------------------------
__device__ __forceinline__ float fsqrt_(float x) { float r; asm("sqrt.approx.f32 %0,%1;" : "=f"(r) : "f"(x)); return r; }
__device__ __forceinline__ float frcp_(float x)  { float r; asm("rcp.approx.f32 %0,%1;"  : "=f"(r) : "f"(x)); return r; }
__device__ __forceinline__ float ftanh_(float x) { float e = __expf(2.0f * x); return 1.0f - 2.0f * frcp_(e + 1.0f); }
__device__ __forceinline__ float fatanh_(float x){ return 0.5f * __logf((1.0f + x) * frcp_(1.0f - x)); }
__device__ __forceinline__ float fasinh_(float x){ float a = fabsf(x); float l = __logf(a + fsqrt_(fmaf(a, a, 1.0f))); return copysignf(l, x); }
__device__ __forceinline__ float fsinh_(float x) { float e = __expf(x); return 0.5f * (e - frcp_(e)); }
__device__ __forceinline__ float fsigm_(float x) { return frcp_(1.0f + __expf(-x)); }

// ---------------- mlr/sinh epilogue ------------------------------------------
__device__ __forceinline__ float fc_elem(float nz, float inz, float coef,
                                         float rb, float y2b, float g)
{
    const float s  = g * inz;
    float alpha = ftanh_(rb * nz);
    float aa = fabsf(alpha);
    if (aa > MAXN) alpha *= MAXN * frcp_(aa);
    const float x2 = alpha * alpha;
    const float xy = -alpha * s;
    const float A  = 1.0f + 2.0f * xy + y2b;
    const float Bc = 1.0f - x2;
    const float den = fmaxf(1.0f + 2.0f * xy + x2 * y2b, EPSN);
    const float inv = frcp_(den);
    float pa = (Bc * s - A * alpha) * inv;
    float p2 = (A * A * x2 - 2.0f * A * Bc * alpha * s + Bc * Bc * y2b) * (inv * inv);
    float pn = fmaxf(fsqrt_(fmaxf(p2, 0.0f)), EPSN);
    if (pn > MAXN) { float f = MAXN * frcp_(pn); pa *= f; p2 *= f * f; }
    const float lam = 2.0f * frcp_(1.0f - p2);
    return fsinh_(coef * fasinh_(pa * lam));
}

// ---------------- K1: 4 fused GEMMs + in-block stats + epilogue --------------
__global__ void __launch_bounds__(256) k1_gemm(
    const float* __restrict__ hidden, const float* __restrict__ hyp_x,
    const float* __restrict__ Wz_z, const float* __restrict__ Wz_r,
    const float* __restrict__ Uz_z, const float* __restrict__ Uz_r,
    const float* __restrict__ Wr_z, const float* __restrict__ Wr_r,
    const float* __restrict__ Ur_z, const float* __restrict__ Ur_r)
{
    const int fc = blockIdx.z;
    const float *X, *Z, *R;
    if      (fc == 0) { X = hidden; Z = Wz_z; R = Wz_r; }
    else if (fc == 1) { X = hyp_x;  Z = Uz_z; R = Uz_r; }
    else if (fc == 2) { X = hidden; Z = Wr_z; R = Wr_r; }
    else              { X = hyp_x;  Z = Ur_z; R = Ur_r; }

    __shared__ float4 Xs[32][17];
    __shared__ float4 Zs[32][17];
    __shared__ float sX[32], sZ[32];   // per-row sumsq of X rows / Z rows

    const int b0 = blockIdx.y * 32, c0 = blockIdx.x * 32;
    const int tid = threadIdx.x;
    const int tx = tid & 15, ty = tid >> 4;

    float a00 = 0.f, a01 = 0.f, a10 = 0.f, a11 = 0.f;
    float xs0 = 0.f, xs1 = 0.f, zs0 = 0.f, zs1 = 0.f;

    for (int kc = 0; kc < 256; kc += 64) {
        // thread loads Xs[ty][tx], Xs[ty+16][tx], Zs[ty][tx], Zs[ty+16][tx]
        float4 vx0 = reinterpret_cast<const float4*>(X + (b0 + ty) * 256 + kc)[tx];
        float4 vx1 = reinterpret_cast<const float4*>(X + (b0 + ty + 16) * 256 + kc)[tx];
        float4 vz0 = reinterpret_cast<const float4*>(Z + (c0 + ty) * 256 + kc)[tx];
        float4 vz1 = reinterpret_cast<const float4*>(Z + (c0 + ty + 16) * 256 + kc)[tx];
        xs0 = fmaf(vx0.x, vx0.x, fmaf(vx0.y, vx0.y, fmaf(vx0.z, vx0.z, fmaf(vx0.w, vx0.w, xs0))));
        xs1 = fmaf(vx1.x, vx1.x, fmaf(vx1.y, vx1.y, fmaf(vx1.z, vx1.z, fmaf(vx1.w, vx1.w, xs1))));
        zs0 = fmaf(vz0.x, vz0.x, fmaf(vz0.y, vz0.y, fmaf(vz0.z, vz0.z, fmaf(vz0.w, vz0.w, zs0))));
        zs1 = fmaf(vz1.x, vz1.x, fmaf(vz1.y, vz1.y, fmaf(vz1.z, vz1.z, fmaf(vz1.w, vz1.w, zs1))));
        Xs[ty][tx] = vx0;  Xs[ty + 16][tx] = vx1;
        Zs[ty][tx] = vz0;  Zs[ty + 16][tx] = vz1;
        __syncthreads();
        #pragma unroll
        for (int q = 0; q < 16; q++) {
            const float4 xA = Xs[ty][q],      xB = Xs[ty + 16][q];
            const float4 zA = Zs[tx][q],      zB = Zs[tx + 16][q];
            a00 = fmaf(xA.x, zA.x, a00); a00 = fmaf(xA.y, zA.y, a00);
            a00 = fmaf(xA.z, zA.z, a00); a00 = fmaf(xA.w, zA.w, a00);
            a01 = fmaf(xA.x, zB.x, a01); a01 = fmaf(xA.y, zB.y, a01);
            a01 = fmaf(xA.z, zB.z, a01); a01 = fmaf(xA.w, zB.w, a01);
            a10 = fmaf(xB.x, zA.x, a10); a10 = fmaf(xB.y, zA.y, a10);
            a10 = fmaf(xB.z, zA.z, a10); a10 = fmaf(xB.w, zA.w, a10);
            a11 = fmaf(xB.x, zB.x, a11); a11 = fmaf(xB.y, zB.y, a11);
            a11 = fmaf(xB.z, zB.z, a11); a11 = fmaf(xB.w, zB.w, a11);
        }
        __syncthreads();
    }

    // reduce row-sumsq across the 16 lanes sharing each row (xor stays in 16-group)
    #pragma unroll
    for (int o = 8; o; o >>= 1) {
        xs0 += __shfl_xor_sync(0xffffffffu, xs0, o);
        xs1 += __shfl_xor_sync(0xffffffffu, xs1, o);
        zs0 += __shfl_xor_sync(0xffffffffu, zs0, o);
        zs1 += __shfl_xor_sync(0xffffffffu, zs1, o);
    }
    if (tx == 0) { sX[ty] = xs0; sX[ty + 16] = xs1; sZ[ty] = zs0; sZ[ty + 16] = zs1; }
    __syncthreads();

    const int bA = b0 + ty, bB = b0 + ty + 16;
    const int cA = c0 + tx, cB = c0 + tx + 16;
    const float y20 = sX[ty], y21 = sX[ty + 16];
    const float nz0 = sqrtf(sZ[tx]), nz1 = sqrtf(sZ[tx + 16]);
    const float inz0 = frcp_(nz0), inz1 = frcp_(nz1);
    const float rb0 = R[bA], rb1 = R[bB];
    // coef = 2*nz/cosh(R[cl])^2
    float ec0 = __expf(R[cA]); float ch0 = 0.5f * (ec0 + frcp_(ec0));
    float ec1 = __expf(R[cB]); float ch1 = 0.5f * (ec1 + frcp_(ec1));
    const float coef0 = 2.0f * nz0 * frcp_(ch0 * ch0);
    const float coef1 = 2.0f * nz1 * frcp_(ch1 * ch1);

    g_w[fc][bA * 256 + cA] = fc_elem(nz0, inz0, coef0, rb0, y20, a00);
    g_w[fc][bA * 256 + cB] = fc_elem(nz1, inz1, coef1, rb0, y20, a01);
    g_w[fc][bB * 256 + cA] = fc_elem(nz0, inz0, coef0, rb1, y21, a10);
    g_w[fc][bB * 256 + cB] = fc_elem(nz1, inz1, coef1, rb1, y21, a11);
}

// ---------------- K1b: per-row scale (warp per row) --------------------------
__global__ void k1b_scale()
{
    const int gw = (blockIdx.x * blockDim.x + threadIdx.x) >> 5;
    const int lane = threadIdx.x & 31;
    const int fc = gw >> 8, row = gw & 255;
    float s = 0.0f;
    #pragma unroll
    for (int i = 0; i < 8; i++) { float w = g_w[fc][row * NB + lane + 32 * i]; s = fmaf(w, w, s); }
    #pragma unroll
    for (int o = 16; o; o >>= 1) s += __shfl_xor_sync(0xffffffffu, s, o);
    if (lane == 0) g_scale[fc][row] = sqrtf(s) + 1.0f;
}

// ---------------- batched block reduction (256 threads, 8 warps) -------------
template<int K>
__device__ __forceinline__ void bred(float* v, float* sm)
{
    const int lane = threadIdx.x & 31, wid = threadIdx.x >> 5;
    __syncthreads();     // protect sm from previous round's readers
    #pragma unroll
    for (int k = 0; k < K; k++) {
        float x = v[k];
        #pragma unroll
        for (int o = 16; o; o >>= 1) x += __shfl_xor_sync(0xffffffffu, x, o);
        if (lane == 0) sm[k * 8 + wid] = x;
    }
    __syncthreads();
    if (threadIdx.x < K) {
        float s = sm[threadIdx.x * 8];
        #pragma unroll
        for (int w = 1; w < 8; w++) s += sm[threadIdx.x * 8 + w];
        sm[threadIdx.x * 8] = s;
    }
    __syncthreads();
    #pragma unroll
    for (int k = 0; k < K; k++) v[k] = sm[k * 8];
}

// ---------------- madd scalar helper -----------------------------------------
struct MS { float A, B, inv, m, nc; };
__device__ __forceinline__ MS madds(float sxx, float syy, float sxy)
{
    MS r;
    r.A = 1.0f + 2.0f * sxy + syy;
    r.B = 1.0f - sxx;
    float den = fmaxf(1.0f + 2.0f * sxy + sxx * syy, EPSN);
    r.inv = frcp_(den);
    float n2 = (r.A * r.A * sxx + 2.0f * r.A * r.B * sxy + r.B * r.B * syy) * r.inv * r.inv;
    float n = fmaxf(fsqrt_(fmaxf(n2, 0.0f)), EPSN);
    r.m = (n > MAXN) ? MAXN * frcp_(n) : 1.0f;
    r.nc = fminf(n, MAXN);
    return r;
}

// ---------------- K2: block per batch row (1 element / thread) ---------------
__global__ void __launch_bounds__(256) k2_final(
    const float* __restrict__ hidden, const float* __restrict__ bz,
    const float* __restrict__ br, const float* __restrict__ bh,
    float* __restrict__ out)
{
    __shared__ float sm[15 * 8];
    const int b = blockIdx.x, j = threadIdx.x;

    const float hid = hidden[b * NB + j];
    const float bhv = bh[j], bzv = bz[j], brv = br[j];
    const float F0 = g_scale[0][j] * g_w[0][b * NB + j];
    const float G0 = g_scale[1][j] * g_w[1][b * NB + j];
    const float F1 = g_scale[2][j] * g_w[2][b * NB + j];
    const float G1 = g_scale[3][j] * g_w[3][b * NB + j];

    // ---- round 1: 15 sums ----
    float v[15];
    v[0] = F0 * F0;  v[1] = G0 * G0;  v[2] = F0 * G0;
    v[3] = F0 * bzv; v[4] = G0 * bzv; v[5] = bzv * bzv;
    v[6] = F1 * F1;  v[7] = G1 * G1;  v[8] = F1 * G1;
    v[9] = F1 * brv; v[10] = G1 * brv; v[11] = brv * brv;
    v[12] = hid * hid; v[13] = bhv * bhv; v[14] = hid * bhv;
    bred<15>(v, sm);
    const float sFF0 = v[0], sGG0 = v[1], sFG0 = v[2], sFb0 = v[3], sGb0 = v[4], sbb0 = v[5];
    const float sFF1 = v[6], sGG1 = v[7], sFG1 = v[8], sFb1 = v[9], sGb1 = v[10], sbb1 = v[11];
    const float shh = v[12], sbhbh = v[13], shbh = v[14];

    // ---- z gate (closed form) ----
    MS z1 = madds(sFF0, sGG0, sFG0);
    float zcF = z1.m * z1.inv * z1.A, zcG = z1.m * z1.inv * z1.B;
    MS z2 = madds(z1.nc * z1.nc, sbb0, zcF * sFb0 + zcG * sGb0);
    float k2a = z2.m * z2.inv * z2.A, k2b = z2.m * z2.inv * z2.B;
    float facz = fatanh_(z2.nc) * frcp_(z2.nc);
    const float zg = fsigm_(facz * (k2a * (zcF * F0 + zcG * G0) + k2b * bzv));

    // ---- r gate ----
    MS r1 = madds(sFF1, sGG1, sFG1);
    float rcF = r1.m * r1.inv * r1.A, rcG = r1.m * r1.inv * r1.B;
    MS r2 = madds(r1.nc * r1.nc, sbb1, rcF * sFb1 + rcG * sGb1);
    float l2a = r2.m * r2.inv * r2.A, l2b = r2.m * r2.inv * r2.B;
    float facr = fatanh_(r2.nc) * frcp_(r2.nc);
    const float rg = fsigm_(facr * (l2a * (rcF * F1 + rcG * G1) + l2b * brv));

    // ---- round 2: 4 sums ----
    float v2[4];
    v2[0] = rg * rg; v2[1] = rg * bhv; v2[2] = hid * rg; v2[3] = zg * zg;
    bred<4>(v2, sm);
    const float srr = v2[0], srbh = v2[1], shr = v2[2], szz = v2[3];

    // ---- h_tilde = madd(rg, bh); mh = madd(-hid, ht) ----
    MS h3 = madds(srr, sbhbh, srbh);
    float hA = h3.m * h3.inv * h3.A, hB = h3.m * h3.inv * h3.B;
    float sht_h = hA * shr + hB * shbh;
    MS h4 = madds(shh, h3.nc * h3.nc, -sht_h);
    float mA = -h4.m * h4.inv * h4.A;
    float mR =  h4.m * h4.inv * h4.B * hA;
    float mB =  h4.m * h4.inv * h4.B * hB;

    // ---- round 3: 2 sums ----
    const float wx = (mA * hid + mR * rg + mB * bhv) * zg;
    float v3[2];
    v3[0] = wx * wx; v3[1] = hid * wx;
    bred<2>(v3, sm);
    const float swx = v3[0], shwx = v3[1];

    // ---- mobius pointwise mul + final add (closed form) ----
    float xn  = fmaxf(fsqrt_(szz), EPSN);
    float wxn = fmaxf(fsqrt_(swx), EPSN);
    float tt  = fatanh_(fminf(xn, CLIPV));
    float f   = ftanh_(wxn * frcp_(xn) * tt);
    float pn  = fmaxf(f, EPSN);
    float cf  = f * frcp_(wxn);
    if (pn > MAXN) cf *= MAXN * frcp_(pn);
    float pnc = fminf(pn, MAXN);

    MS o5 = madds(shh, pnc * pnc, cf * shwx);
    float oH = o5.m * o5.inv * o5.A, oP = o5.m * o5.inv * o5.B * cf;

    out[b * NB + j] = oH * hid + oP * wx;
}

// ---------------- launch ------------------------------------------------------
extern "C" void kernel_launch(void* const* d_in, const int* in_sizes, int n_in,
                              void* d_out, int out_size)
{
    const float* hyp_x  = (const float*)d_in[0];
    const float* hidden = (const float*)d_in[1];
    const float* Wz_z   = (const float*)d_in[2];
    const float* Wz_r   = (const float*)d_in[3];
    const float* Uz_z   = (const float*)d_in[4];
    const float* Uz_r   = (const float*)d_in[5];
    const float* Wr_z   = (const float*)d_in[6];
    const float* Wr_r   = (const float*)d_in[7];
    const float* Ur_z   = (const float*)d_in[8];
    const float* Ur_r   = (const float*)d_in[9];
    const float* b_z    = (const float*)d_in[14];
    const float* b_r    = (const float*)d_in[15];
    const float* b_h    = (const float*)d_in[16];
    float* out = (float*)d_out;

    k1_gemm<<<dim3(8, 8, 4), 256>>>(hidden, hyp_x, Wz_z, Wz_r, Uz_z, Uz_r,
                                    Wr_z, Wr_r, Ur_z, Ur_r);
    k1b_scale<<<128, 256>>>();
    k2_final<<<256, 256>>>(hidden, b_z, b_r, b_h, out);
}

// round 5
// speedup vs baseline: 1.1618x; 1.1618x over previous
#include <cuda_runtime.h>
#include <math.h>

// B = H = IN = 256, c = 1. Dead code (Wh*/Uh*, r_point_h) skipped.

#define NB 256
#define MAXN 0.996f          // (1 - 4e-3)/sqrt(c)
#define EPSN 1e-15f
#define CLIPV 0.9999999f     // 1 - 1e-7 in f32

// ---------------- scratch ---------------------------------------------------
__device__ float g_w[4][NB * NB];     // w = sinh(mlr logits) per fc, [b][cl]
__device__ float g_scale[4][NB];      // sqrt(row-sumsq of w)+1

// ---------------- fast math helpers -----------------------------------------
__device__ __forceinline__ float fsqrt_(float x) { float r; asm("sqrt.approx.f32 %0,%1;" : "=f"(r) : "f"(x)); return r; }
__device__ __forceinline__ float frcp_(float x)  { float r; asm("rcp.approx.f32 %0,%1;"  : "=f"(r) : "f"(x)); return r; }
__device__ __forceinline__ float ftanh_(float x) { float e = __expf(2.0f * x); return 1.0f - 2.0f * frcp_(e + 1.0f); }
__device__ __forceinline__ float fatanh_(float x){ return 0.5f * __logf((1.0f + x) * frcp_(1.0f - x)); }
__device__ __forceinline__ float fasinh_(float x){ float a = fabsf(x); float l = __logf(a + fsqrt_(fmaf(a, a, 1.0f))); return copysignf(l, x); }
__device__ __forceinline__ float fsinh_(float x) { float e = __expf(x); return 0.5f * (e - frcp_(e)); }
__device__ __forceinline__ float fsigm_(float x) { return frcp_(1.0f + __expf(-x)); }

// ---------------- mlr/sinh epilogue ------------------------------------------
__device__ __forceinline__ float fc_elem(float nz, float inz, float coef,
                                         float rb, float y2b, float g)
{
    const float s  = g * inz;
    float alpha = ftanh_(rb * nz);
    float aa = fabsf(alpha);
    if (aa > MAXN) alpha *= MAXN * frcp_(aa);
    const float x2 = alpha * alpha;
    const float xy = -alpha * s;
    const float A  = 1.0f + 2.0f * xy + y2b;
    const float Bc = 1.0f - x2;
    const float den = fmaxf(1.0f + 2.0f * xy + x2 * y2b, EPSN);
    const float inv = frcp_(den);
    float pa = (Bc * s - A * alpha) * inv;
    float p2 = (A * A * x2 - 2.0f * A * Bc * alpha * s + Bc * Bc * y2b) * (inv * inv);
    float pn = fmaxf(fsqrt_(fmaxf(p2, 0.0f)), EPSN);
    if (pn > MAXN) { float f = MAXN * frcp_(pn); pa *= f; p2 *= f * f; }
    const float lam = 2.0f * frcp_(1.0f - p2);
    return fsinh_(coef * fasinh_(pa * lam));
}

// ---------------- K1: 4 GEMMs, 32x64 tile, 4x4 microtile, 128 threads --------
// grid (4 n-tiles, 8 m-tiles, 4 fc). K chunked by 64, register prefetch.
__global__ void __launch_bounds__(128) k1_gemm(
    const float* __restrict__ hidden, const float* __restrict__ hyp_x,
    const float* __restrict__ Wz_z, const float* __restrict__ Wz_r,
    const float* __restrict__ Uz_z, const float* __restrict__ Uz_r,
    const float* __restrict__ Wr_z, const float* __restrict__ Wr_r,
    const float* __restrict__ Ur_z, const float* __restrict__ Ur_r)
{
    const int fc = blockIdx.z;
    const float *X, *Z, *R;
    if      (fc == 0) { X = hidden; Z = Wz_z; R = Wz_r; }
    else if (fc == 1) { X = hyp_x;  Z = Uz_z; R = Uz_r; }
    else if (fc == 2) { X = hidden; Z = Wr_z; R = Wr_r; }
    else              { X = hyp_x;  Z = Ur_z; R = Ur_r; }

    __shared__ float4 Xs4[32][17];   // 32 rows x 64 k (float4), pitch 17
    __shared__ float4 Zs4[64][17];   // 64 rows x 64 k
    __shared__ float sX[32], sZ[64];

    const int b0 = blockIdx.y * 32, c0 = blockIdx.x * 64;
    const int tid = threadIdx.x;
    const int ty = tid >> 4;      // 0..7  (m groups, m = ty + 8i)
    const int tx = tid & 15;      // 0..15 (n groups, n = tx + 16j)

    const float4* Xg = reinterpret_cast<const float4*>(X) + (b0 + ty) * 64 + tx;
    const float4* Zg = reinterpret_cast<const float4*>(Z) + (c0 + ty) * 64 + tx;

    float4 rx[4], rz[8];
    float xss[4] = {0.f, 0.f, 0.f, 0.f};
    float zss[8] = {0.f, 0.f, 0.f, 0.f, 0.f, 0.f, 0.f, 0.f};
    float a[4][4];
    #pragma unroll
    for (int i = 0; i < 4; i++)
        #pragma unroll
        for (int j = 0; j < 4; j++) a[i][j] = 0.f;

    // prefetch chunk 0
    #pragma unroll
    for (int p = 0; p < 4; p++) rx[p] = Xg[512 * p];
    #pragma unroll
    for (int p = 0; p < 8; p++) rz[p] = Zg[512 * p];

    #pragma unroll
    for (int c = 0; c < 4; c++) {
        // store staged chunk + accumulate row sumsq
        #pragma unroll
        for (int p = 0; p < 4; p++) {
            float4 v = rx[p];
            Xs4[ty + 8 * p][tx] = v;
            xss[p] = fmaf(v.x, v.x, fmaf(v.y, v.y, fmaf(v.z, v.z, fmaf(v.w, v.w, xss[p]))));
        }
        #pragma unroll
        for (int p = 0; p < 8; p++) {
            float4 v = rz[p];
            Zs4[ty + 8 * p][tx] = v;
            zss[p] = fmaf(v.x, v.x, fmaf(v.y, v.y, fmaf(v.z, v.z, fmaf(v.w, v.w, zss[p]))));
        }
        __syncthreads();

        // prefetch next chunk into registers (hidden behind FMA loop)
        if (c < 3) {
            const int kq = 16 * (c + 1);
            #pragma unroll
            for (int p = 0; p < 4; p++) rx[p] = Xg[512 * p + kq];
            #pragma unroll
            for (int p = 0; p < 8; p++) rz[p] = Zg[512 * p + kq];
        }

        // FMA over this chunk
        #pragma unroll
        for (int k4 = 0; k4 < 16; k4++) {
            float4 xv[4], zv[4];
            #pragma unroll
            for (int i = 0; i < 4; i++) xv[i] = Xs4[ty + 8 * i][k4];
            #pragma unroll
            for (int j = 0; j < 4; j++) zv[j] = Zs4[tx + 16 * j][k4];
            #pragma unroll
            for (int i = 0; i < 4; i++)
                #pragma unroll
                for (int j = 0; j < 4; j++) {
                    a[i][j] = fmaf(xv[i].x, zv[j].x, a[i][j]);
                    a[i][j] = fmaf(xv[i].y, zv[j].y, a[i][j]);
                    a[i][j] = fmaf(xv[i].z, zv[j].z, a[i][j]);
                    a[i][j] = fmaf(xv[i].w, zv[j].w, a[i][j]);
                }
        }
        __syncthreads();
    }

    // reduce row sumsq across the 16 lanes sharing each row group
    #pragma unroll
    for (int o = 8; o; o >>= 1) {
        #pragma unroll
        for (int p = 0; p < 4; p++) xss[p] += __shfl_xor_sync(0xffffffffu, xss[p], o);
        #pragma unroll
        for (int p = 0; p < 8; p++) zss[p] += __shfl_xor_sync(0xffffffffu, zss[p], o);
    }
    if (tx == 0) {
        #pragma unroll
        for (int p = 0; p < 4; p++) sX[ty + 8 * p] = xss[p];
        #pragma unroll
        for (int p = 0; p < 8; p++) sZ[ty + 8 * p] = zss[p];
    }
    __syncthreads();

    // epilogue
    float y2[4], rbv[4];
    #pragma unroll
    for (int i = 0; i < 4; i++) { y2[i] = sX[ty + 8 * i]; rbv[i] = R[b0 + ty + 8 * i]; }
    float nzv[4], inzv[4], coefv[4];
    #pragma unroll
    for (int j = 0; j < 4; j++) {
        float nz = sqrtf(sZ[tx + 16 * j]);
        nzv[j] = nz; inzv[j] = frcp_(nz);
        float e = __expf(R[c0 + tx + 16 * j]);
        float ch = 0.5f * (e + frcp_(e));
        coefv[j] = 2.0f * nz * frcp_(ch * ch);
    }
    float* wout = g_w[fc];
    #pragma unroll
    for (int i = 0; i < 4; i++) {
        const int row = (b0 + ty + 8 * i) * 256 + c0 + tx;
        #pragma unroll
        for (int j = 0; j < 4; j++)
            wout[row + 16 * j] = fc_elem(nzv[j], inzv[j], coefv[j], rbv[i], y2[i], a[i][j]);
    }
}

// ---------------- K1b: per-row scale (warp per row) --------------------------
__global__ void k1b_scale()
{
    const int gw = (blockIdx.x * blockDim.x + threadIdx.x) >> 5;
    const int lane = threadIdx.x & 31;
    const int fc = gw >> 8, row = gw & 255;
    float s = 0.0f;
    #pragma unroll
    for (int i = 0; i < 8; i++) { float w = g_w[fc][row * NB + lane + 32 * i]; s = fmaf(w, w, s); }
    #pragma unroll
    for (int o = 16; o; o >>= 1) s += __shfl_xor_sync(0xffffffffu, s, o);
    if (lane == 0) g_scale[fc][row] = sqrtf(s) + 1.0f;
}

// ---------------- batched block reduction (256 threads, 8 warps) -------------
template<int K>
__device__ __forceinline__ void bred(float* v, float* sm)
{
    const int lane = threadIdx.x & 31, wid = threadIdx.x >> 5;
    __syncthreads();     // protect sm from previous round's readers
    #pragma unroll
    for (int k = 0; k < K; k++) {
        float x = v[k];
        #pragma unroll
        for (int o = 16; o; o >>= 1) x += __shfl_xor_sync(0xffffffffu, x, o);
        if (lane == 0) sm[k * 8 + wid] = x;
    }
    __syncthreads();
    if (threadIdx.x < K) {
        float s = sm[threadIdx.x * 8];
        #pragma unroll
        for (int w = 1; w < 8; w++) s += sm[threadIdx.x * 8 + w];
        sm[threadIdx.x * 8] = s;
    }
    __syncthreads();
    #pragma unroll
    for (int k = 0; k < K; k++) v[k] = sm[k * 8];
}

// ---------------- madd scalar helper -----------------------------------------
struct MS { float A, B, inv, m, nc; };
__device__ __forceinline__ MS madds(float sxx, float syy, float sxy)
{
    MS r;
    r.A = 1.0f + 2.0f * sxy + syy;
    r.B = 1.0f - sxx;
    float den = fmaxf(1.0f + 2.0f * sxy + sxx * syy, EPSN);
    r.inv = frcp_(den);
    float n2 = (r.A * r.A * sxx + 2.0f * r.A * r.B * sxy + r.B * r.B * syy) * r.inv * r.inv;
    float n = fmaxf(fsqrt_(fmaxf(n2, 0.0f)), EPSN);
    r.m = (n > MAXN) ? MAXN * frcp_(n) : 1.0f;
    r.nc = fminf(n, MAXN);
    return r;
}

// ---------------- K2: block per batch row (1 element / thread) ---------------
__global__ void __launch_bounds__(256) k2_final(
    const float* __restrict__ hidden, const float* __restrict__ bz,
    const float* __restrict__ br, const float* __restrict__ bh,
    float* __restrict__ out)
{
    __shared__ float sm[15 * 8];
    const int b = blockIdx.x, j = threadIdx.x;

    const float hid = hidden[b * NB + j];
    const float bhv = bh[j], bzv = bz[j], brv = br[j];
    const float F0 = g_scale[0][j] * g_w[0][b * NB + j];
    const float G0 = g_scale[1][j] * g_w[1][b * NB + j];
    const float F1 = g_scale[2][j] * g_w[2][b * NB + j];
    const float G1 = g_scale[3][j] * g_w[3][b * NB + j];

    // ---- round 1: 15 sums ----
    float v[15];
    v[0] = F0 * F0;  v[1] = G0 * G0;  v[2] = F0 * G0;
    v[3] = F0 * bzv; v[4] = G0 * bzv; v[5] = bzv * bzv;
    v[6] = F1 * F1;  v[7] = G1 * G1;  v[8] = F1 * G1;
    v[9] = F1 * brv; v[10] = G1 * brv; v[11] = brv * brv;
    v[12] = hid * hid; v[13] = bhv * bhv; v[14] = hid * bhv;
    bred<15>(v, sm);
    const float sFF0 = v[0], sGG0 = v[1], sFG0 = v[2], sFb0 = v[3], sGb0 = v[4], sbb0 = v[5];
    const float sFF1 = v[6], sGG1 = v[7], sFG1 = v[8], sFb1 = v[9], sGb1 = v[10], sbb1 = v[11];
    const float shh = v[12], sbhbh = v[13], shbh = v[14];

    // ---- z gate (closed form) ----
    MS z1 = madds(sFF0, sGG0, sFG0);
    float zcF = z1.m * z1.inv * z1.A, zcG = z1.m * z1.inv * z1.B;
    MS z2 = madds(z1.nc * z1.nc, sbb0, zcF * sFb0 + zcG * sGb0);
    float k2a = z2.m * z2.inv * z2.A, k2b = z2.m * z2.inv * z2.B;
    float facz = fatanh_(z2.nc) * frcp_(z2.nc);
    const float zg = fsigm_(facz * (k2a * (zcF * F0 + zcG * G0) + k2b * bzv));

    // ---- r gate ----
    MS r1 = madds(sFF1, sGG1, sFG1);
    float rcF = r1.m * r1.inv * r1.A, rcG = r1.m * r1.inv * r1.B;
    MS r2 = madds(r1.nc * r1.nc, sbb1, rcF * sFb1 + rcG * sGb1);
    float l2a = r2.m * r2.inv * r2.A, l2b = r2.m * r2.inv * r2.B;
    float facr = fatanh_(r2.nc) * frcp_(r2.nc);
    const float rg = fsigm_(facr * (l2a * (rcF * F1 + rcG * G1) + l2b * brv));

    // ---- round 2: 4 sums ----
    float v2[4];
    v2[0] = rg * rg; v2[1] = rg * bhv; v2[2] = hid * rg; v2[3] = zg * zg;
    bred<4>(v2, sm);
    const float srr = v2[0], srbh = v2[1], shr = v2[2], szz = v2[3];

    // ---- h_tilde = madd(rg, bh); mh = madd(-hid, ht) ----
    MS h3 = madds(srr, sbhbh, srbh);
    float hA = h3.m * h3.inv * h3.A, hB = h3.m * h3.inv * h3.B;
    float sht_h = hA * shr + hB * shbh;
    MS h4 = madds(shh, h3.nc * h3.nc, -sht_h);
    float mA = -h4.m * h4.inv * h4.A;
    float mR =  h4.m * h4.inv * h4.B * hA;
    float mB =  h4.m * h4.inv * h4.B * hB;

    // ---- round 3: 2 sums ----
    const float wx = (mA * hid + mR * rg + mB * bhv) * zg;
    float v3[2];
    v3[0] = wx * wx; v3[1] = hid * wx;
    bred<2>(v3, sm);
    const float swx = v3[0], shwx = v3[1];

    // ---- mobius pointwise mul + final add (closed form) ----
    float xn  = fmaxf(fsqrt_(szz), EPSN);
    float wxn = fmaxf(fsqrt_(swx), EPSN);
    float tt  = fatanh_(fminf(xn, CLIPV));
    float f   = ftanh_(wxn * frcp_(xn) * tt);
    float pn  = fmaxf(f, EPSN);
    float cf  = f * frcp_(wxn);
    if (pn > MAXN) cf *= MAXN * frcp_(pn);
    float pnc = fminf(pn, MAXN);

    MS o5 = madds(shh, pnc * pnc, cf * shwx);
    float oH = o5.m * o5.inv * o5.A, oP = o5.m * o5.inv * o5.B * cf;

    out[b * NB + j] = oH * hid + oP * wx;
}

// ---------------- launch ------------------------------------------------------
extern "C" void kernel_launch(void* const* d_in, const int* in_sizes, int n_in,
                              void* d_out, int out_size)
{
    const float* hyp_x  = (const float*)d_in[0];
    const float* hidden = (const float*)d_in[1];
    const float* Wz_z   = (const float*)d_in[2];
    const float* Wz_r   = (const float*)d_in[3];
    const float* Uz_z   = (const float*)d_in[4];
    const float* Uz_r   = (const float*)d_in[5];
    const float* Wr_z   = (const float*)d_in[6];
    const float* Wr_r   = (const float*)d_in[7];
    const float* Ur_z   = (const float*)d_in[8];
    const float* Ur_r   = (const float*)d_in[9];
    const float* b_z    = (const float*)d_in[14];
    const float* b_r    = (const float*)d_in[15];
    const float* b_h    = (const float*)d_in[16];
    float* out = (float*)d_out;

    k1_gemm<<<dim3(4, 8, 4), 128>>>(hidden, hyp_x, Wz_z, Wz_r, Uz_z, Uz_r,
                                    Wr_z, Wr_r, Ur_z, Ur_r);
    k1b_scale<<<128, 256>>>();
    k2_final<<<256, 256>>>(hidden, b_z, b_r, b_h, out);
}

// round 6
// speedup vs baseline: 1.3035x; 1.1220x over previous
#include <cuda_runtime.h>
#include <math.h>

// B = H = IN = 256, c = 1. Dead code (Wh*/Uh*, r_point_h) skipped.

#define NB 256
#define MAXN 0.996f          // (1 - 4e-3)/sqrt(c)
#define EPSN 1e-15f
#define CLIPV 0.9999999f     // 1 - 1e-7 in f32

// ---------------- scratch ---------------------------------------------------
__device__ float g_w[4][NB * NB];     // w = sinh(mlr logits) per fc, [b][cl]
__device__ float g_scale[4][NB];      // sqrt(row-sumsq of w)+1
__device__ float g_nz[4][NB];         // ||z_cl||
__device__ float g_coef[4][NB];       // 2*||z_cl||/cosh(r_cl)^2
__device__ float g_y2[2][NB];         // ||x_b||^2 : [0]=hidden, [1]=hyp_x

// ---------------- fast math helpers -----------------------------------------
__device__ __forceinline__ float fsqrt_(float x) { float r; asm("sqrt.approx.f32 %0,%1;" : "=f"(r) : "f"(x)); return r; }
__device__ __forceinline__ float frcp_(float x)  { float r; asm("rcp.approx.f32 %0,%1;"  : "=f"(r) : "f"(x)); return r; }
__device__ __forceinline__ float ftanh_(float x) { float e = __expf(2.0f * x); return 1.0f - 2.0f * frcp_(e + 1.0f); }
__device__ __forceinline__ float fatanh_(float x){ return 0.5f * __logf((1.0f + x) * frcp_(1.0f - x)); }
__device__ __forceinline__ float fasinh_(float x){ float a = fabsf(x); float l = __logf(a + fsqrt_(fmaf(a, a, 1.0f))); return copysignf(l, x); }
__device__ __forceinline__ float fsinh_(float x) { float e = __expf(x); return 0.5f * (e - frcp_(e)); }
__device__ __forceinline__ float fsigm_(float x) { return frcp_(1.0f + __expf(-x)); }

__device__ __forceinline__ float wsum8(float v) {
    #pragma unroll
    for (int o = 16; o; o >>= 1) v += __shfl_xor_sync(0xffffffffu, v, o);
    return v;
}

// ---------------- K0: per-row stats (warp per row) ---------------------------
__global__ void k0_stats(const float* __restrict__ Wz_z, const float* __restrict__ Wz_r,
                         const float* __restrict__ Uz_z, const float* __restrict__ Uz_r,
                         const float* __restrict__ Wr_z, const float* __restrict__ Wr_r,
                         const float* __restrict__ Ur_z, const float* __restrict__ Ur_r,
                         const float* __restrict__ hidden, const float* __restrict__ hyp_x)
{
    const int gw = (blockIdx.x * blockDim.x + threadIdx.x) >> 5;
    const int lane = threadIdx.x & 31;
    const int m = gw >> 8, row = gw & 255;
    const float* p;
    if      (m == 0) p = Wz_z;
    else if (m == 1) p = Uz_z;
    else if (m == 2) p = Wr_z;
    else if (m == 3) p = Ur_z;
    else if (m == 4) p = hidden;
    else             p = hyp_x;

    // 8 elements per lane as 2 float4 loads
    const float4* p4 = reinterpret_cast<const float4*>(p + row * NB);
    float4 v0 = p4[lane], v1 = p4[lane + 32];
    float s = v0.x*v0.x + v0.y*v0.y + v0.z*v0.z + v0.w*v0.w
            + v1.x*v1.x + v1.y*v1.y + v1.z*v1.z + v1.w*v1.w;
    s = wsum8(s);
    if (lane == 0) {
        if (m < 4) {
            const float* R;
            if      (m == 0) R = Wz_r;
            else if (m == 1) R = Uz_r;
            else if (m == 2) R = Wr_r;
            else             R = Ur_r;
            float nz = sqrtf(s);
            g_nz[m][row] = nz;
            float ch = coshf(R[row]);
            g_coef[m][row] = 2.0f * nz / (ch * ch);
        } else {
            g_y2[m - 4][row] = s;
        }
    }
}

// ---------------- mlr/sinh epilogue ------------------------------------------
__device__ __forceinline__ float fc_elem(int fc, int cl, float rb, float y2b, float g)
{
    const float nz = g_nz[fc][cl];
    const float s  = g * frcp_(nz);
    float alpha = ftanh_(rb * nz);
    float aa = fabsf(alpha);
    if (aa > MAXN) alpha *= MAXN * frcp_(aa);
    const float x2 = alpha * alpha;
    const float xy = -alpha * s;
    const float A  = 1.0f + 2.0f * xy + y2b;
    const float Bc = 1.0f - x2;
    const float den = fmaxf(1.0f + 2.0f * xy + x2 * y2b, EPSN);
    const float inv = frcp_(den);
    float pa = (Bc * s - A * alpha) * inv;
    float p2 = (A * A * x2 - 2.0f * A * Bc * alpha * s + Bc * Bc * y2b) * (inv * inv);
    float pn = fmaxf(fsqrt_(fmaxf(p2, 0.0f)), EPSN);
    if (pn > MAXN) { float f = MAXN * frcp_(pn); pa *= f; p2 *= f * f; }
    const float lam = 2.0f * frcp_(1.0f - p2);
    return fsinh_(g_coef[fc][cl] * fasinh_(pa * lam));
}

// ---------------- K1: 4 fused GEMMs + epilogue (R2 structure) ----------------
__global__ void k1_gemm(const float* __restrict__ hidden, const float* __restrict__ hyp_x,
                        const float* __restrict__ Wz_z, const float* __restrict__ Wz_r,
                        const float* __restrict__ Uz_z, const float* __restrict__ Uz_r,
                        const float* __restrict__ Wr_z, const float* __restrict__ Wr_r,
                        const float* __restrict__ Ur_z, const float* __restrict__ Ur_r)
{
    const int fc = blockIdx.z;
    const float *X, *Z, *R;
    int ysel;
    if      (fc == 0) { X = hidden; Z = Wz_z; R = Wz_r; ysel = 0; }
    else if (fc == 1) { X = hyp_x;  Z = Uz_z; R = Uz_r; ysel = 1; }
    else if (fc == 2) { X = hidden; Z = Wr_z; R = Wr_r; ysel = 0; }
    else              { X = hyp_x;  Z = Ur_z; R = Ur_r; ysel = 1; }

    __shared__ float4 Xs[32][17];
    __shared__ float4 Zs[32][17];

    const int b0 = blockIdx.y * 32, c0 = blockIdx.x * 32;
    const int tid = threadIdx.x;
    const int tx = tid & 15, ty = tid >> 4;

    float a00 = 0.f, a01 = 0.f, a10 = 0.f, a11 = 0.f;

    for (int kc = 0; kc < 256; kc += 64) {
        #pragma unroll
        for (int i = tid; i < 512; i += 256) {
            const int r = i >> 4, c = i & 15;
            Xs[r][c] = reinterpret_cast<const float4*>(X + (b0 + r) * 256 + kc)[c];
            Zs[r][c] = reinterpret_cast<const float4*>(Z + (c0 + r) * 256 + kc)[c];
        }
        __syncthreads();
        #pragma unroll
        for (int q = 0; q < 16; q++) {
            const float4 xA = Xs[ty][q],      xB = Xs[ty + 16][q];
            const float4 zA = Zs[tx][q],      zB = Zs[tx + 16][q];
            a00 = fmaf(xA.x, zA.x, a00); a00 = fmaf(xA.y, zA.y, a00);
            a00 = fmaf(xA.z, zA.z, a00); a00 = fmaf(xA.w, zA.w, a00);
            a01 = fmaf(xA.x, zB.x, a01); a01 = fmaf(xA.y, zB.y, a01);
            a01 = fmaf(xA.z, zB.z, a01); a01 = fmaf(xA.w, zB.w, a01);
            a10 = fmaf(xB.x, zA.x, a10); a10 = fmaf(xB.y, zA.y, a10);
            a10 = fmaf(xB.z, zA.z, a10); a10 = fmaf(xB.w, zA.w, a10);
            a11 = fmaf(xB.x, zB.x, a11); a11 = fmaf(xB.y, zB.y, a11);
            a11 = fmaf(xB.z, zB.z, a11); a11 = fmaf(xB.w, zB.w, a11);
        }
        __syncthreads();
    }

    const int bA = b0 + ty, bB = b0 + ty + 16;
    const int cA = c0 + tx, cB = c0 + tx + 16;
    const float rb0 = R[bA], rb1 = R[bB];
    const float y20 = g_y2[ysel][bA], y21 = g_y2[ysel][bB];

    g_w[fc][bA * 256 + cA] = fc_elem(fc, cA, rb0, y20, a00);
    g_w[fc][bA * 256 + cB] = fc_elem(fc, cB, rb0, y20, a01);
    g_w[fc][bB * 256 + cA] = fc_elem(fc, cA, rb1, y21, a10);
    g_w[fc][bB * 256 + cB] = fc_elem(fc, cB, rb1, y21, a11);
}

// ---------------- K1b: per-row scale (warp per row, float4 loads) ------------
__global__ void k1b_scale()
{
    const int gw = (blockIdx.x * blockDim.x + threadIdx.x) >> 5;
    const int lane = threadIdx.x & 31;
    const int fc = gw >> 8, row = gw & 255;
    const float4* p4 = reinterpret_cast<const float4*>(&g_w[fc][row * NB]);
    float4 v0 = p4[lane], v1 = p4[lane + 32];
    float s = v0.x*v0.x + v0.y*v0.y + v0.z*v0.z + v0.w*v0.w
            + v1.x*v1.x + v1.y*v1.y + v1.z*v1.z + v1.w*v1.w;
    s = wsum8(s);
    if (lane == 0) g_scale[fc][row] = sqrtf(s) + 1.0f;
}

// ---------------- batched block reduction (256 threads, 8 warps) -------------
template<int K>
__device__ __forceinline__ void bred(float* v, float* sm)
{
    const int lane = threadIdx.x & 31, wid = threadIdx.x >> 5;
    __syncthreads();     // protect sm from previous round's readers
    #pragma unroll
    for (int k = 0; k < K; k++) {
        float x = v[k];
        #pragma unroll
        for (int o = 16; o; o >>= 1) x += __shfl_xor_sync(0xffffffffu, x, o);
        if (lane == 0) sm[k * 8 + wid] = x;
    }
    __syncthreads();
    if (threadIdx.x < K) {
        float s = sm[threadIdx.x * 8];
        #pragma unroll
        for (int w = 1; w < 8; w++) s += sm[threadIdx.x * 8 + w];
        sm[threadIdx.x * 8] = s;
    }
    __syncthreads();
    #pragma unroll
    for (int k = 0; k < K; k++) v[k] = sm[k * 8];
}

// ---------------- madd scalar helper -----------------------------------------
struct MS { float A, B, inv, m, nc; };
__device__ __forceinline__ MS madds(float sxx, float syy, float sxy)
{
    MS r;
    r.A = 1.0f + 2.0f * sxy + syy;
    r.B = 1.0f - sxx;
    float den = fmaxf(1.0f + 2.0f * sxy + sxx * syy, EPSN);
    r.inv = frcp_(den);
    float n2 = (r.A * r.A * sxx + 2.0f * r.A * r.B * sxy + r.B * r.B * syy) * r.inv * r.inv;
    float n = fmaxf(fsqrt_(fmaxf(n2, 0.0f)), EPSN);
    r.m = (n > MAXN) ? MAXN * frcp_(n) : 1.0f;
    r.nc = fminf(n, MAXN);
    return r;
}

// ---------------- K2: block per batch row (1 element / thread) ---------------
__global__ void __launch_bounds__(256) k2_final(
    const float* __restrict__ hidden, const float* __restrict__ bz,
    const float* __restrict__ br, const float* __restrict__ bh,
    float* __restrict__ out)
{
    __shared__ float sm[15 * 8];
    const int b = blockIdx.x, j = threadIdx.x;

    const float hid = hidden[b * NB + j];
    const float bhv = bh[j], bzv = bz[j], brv = br[j];
    const float F0 = g_scale[0][j] * g_w[0][b * NB + j];
    const float G0 = g_scale[1][j] * g_w[1][b * NB + j];
    const float F1 = g_scale[2][j] * g_w[2][b * NB + j];
    const float G1 = g_scale[3][j] * g_w[3][b * NB + j];

    // ---- round 1: 15 sums ----
    float v[15];
    v[0] = F0 * F0;  v[1] = G0 * G0;  v[2] = F0 * G0;
    v[3] = F0 * bzv; v[4] = G0 * bzv; v[5] = bzv * bzv;
    v[6] = F1 * F1;  v[7] = G1 * G1;  v[8] = F1 * G1;
    v[9] = F1 * brv; v[10] = G1 * brv; v[11] = brv * brv;
    v[12] = hid * hid; v[13] = bhv * bhv; v[14] = hid * bhv;
    bred<15>(v, sm);
    const float sFF0 = v[0], sGG0 = v[1], sFG0 = v[2], sFb0 = v[3], sGb0 = v[4], sbb0 = v[5];
    const float sFF1 = v[6], sGG1 = v[7], sFG1 = v[8], sFb1 = v[9], sGb1 = v[10], sbb1 = v[11];
    const float shh = v[12], sbhbh = v[13], shbh = v[14];

    // ---- z gate (closed form) ----
    MS z1 = madds(sFF0, sGG0, sFG0);
    float zcF = z1.m * z1.inv * z1.A, zcG = z1.m * z1.inv * z1.B;
    MS z2 = madds(z1.nc * z1.nc, sbb0, zcF * sFb0 + zcG * sGb0);
    float k2a = z2.m * z2.inv * z2.A, k2b = z2.m * z2.inv * z2.B;
    float facz = fatanh_(z2.nc) * frcp_(z2.nc);
    const float zg = fsigm_(facz * (k2a * (zcF * F0 + zcG * G0) + k2b * bzv));

    // ---- r gate ----
    MS r1 = madds(sFF1, sGG1, sFG1);
    float rcF = r1.m * r1.inv * r1.A, rcG = r1.m * r1.inv * r1.B;
    MS r2 = madds(r1.nc * r1.nc, sbb1, rcF * sFb1 + rcG * sGb1);
    float l2a = r2.m * r2.inv * r2.A, l2b = r2.m * r2.inv * r2.B;
    float facr = fatanh_(r2.nc) * frcp_(r2.nc);
    const float rg = fsigm_(facr * (l2a * (rcF * F1 + rcG * G1) + l2b * brv));

    // ---- round 2: 4 sums ----
    float v2[4];
    v2[0] = rg * rg; v2[1] = rg * bhv; v2[2] = hid * rg; v2[3] = zg * zg;
    bred<4>(v2, sm);
    const float srr = v2[0], srbh = v2[1], shr = v2[2], szz = v2[3];

    // ---- h_tilde = madd(rg, bh); mh = madd(-hid, ht) ----
    MS h3 = madds(srr, sbhbh, srbh);
    float hA = h3.m * h3.inv * h3.A, hB = h3.m * h3.inv * h3.B;
    float sht_h = hA * shr + hB * shbh;
    MS h4 = madds(shh, h3.nc * h3.nc, -sht_h);
    float mA = -h4.m * h4.inv * h4.A;
    float mR =  h4.m * h4.inv * h4.B * hA;
    float mB =  h4.m * h4.inv * h4.B * hB;

    // ---- round 3: 2 sums ----
    const float wx = (mA * hid + mR * rg + mB * bhv) * zg;
    float v3[2];
    v3[0] = wx * wx; v3[1] = hid * wx;
    bred<2>(v3, sm);
    const float swx = v3[0], shwx = v3[1];

    // ---- mobius pointwise mul + final add (closed form) ----
    float xn  = fmaxf(fsqrt_(szz), EPSN);
    float wxn = fmaxf(fsqrt_(swx), EPSN);
    float tt  = fatanh_(fminf(xn, CLIPV));
    float f   = ftanh_(wxn * frcp_(xn) * tt);
    float pn  = fmaxf(f, EPSN);
    float cf  = f * frcp_(wxn);
    if (pn > MAXN) cf *= MAXN * frcp_(pn);
    float pnc = fminf(pn, MAXN);

    MS o5 = madds(shh, pnc * pnc, cf * shwx);
    float oH = o5.m * o5.inv * o5.A, oP = o5.m * o5.inv * o5.B * cf;

    out[b * NB + j] = oH * hid + oP * wx;
}

// ---------------- launch ------------------------------------------------------
extern "C" void kernel_launch(void* const* d_in, const int* in_sizes, int n_in,
                              void* d_out, int out_size)
{
    const float* hyp_x  = (const float*)d_in[0];
    const float* hidden = (const float*)d_in[1];
    const float* Wz_z   = (const float*)d_in[2];
    const float* Wz_r   = (const float*)d_in[3];
    const float* Uz_z   = (const float*)d_in[4];
    const float* Uz_r   = (const float*)d_in[5];
    const float* Wr_z   = (const float*)d_in[6];
    const float* Wr_r   = (const float*)d_in[7];
    const float* Ur_z   = (const float*)d_in[8];
    const float* Ur_r   = (const float*)d_in[9];
    const float* b_z    = (const float*)d_in[14];
    const float* b_r    = (const float*)d_in[15];
    const float* b_h    = (const float*)d_in[16];
    float* out = (float*)d_out;

    k0_stats<<<192, 256>>>(Wz_z, Wz_r, Uz_z, Uz_r, Wr_z, Wr_r, Ur_z, Ur_r, hidden, hyp_x);
    k1_gemm<<<dim3(8, 8, 4), 256>>>(hidden, hyp_x, Wz_z, Wz_r, Uz_z, Uz_r,
                                    Wr_z, Wr_r, Ur_z, Ur_r);
    k1b_scale<<<128, 256>>>();
    k2_final<<<256, 256>>>(hidden, b_z, b_r, b_h, out);
}

// round 7
// speedup vs baseline: 1.4031x; 1.0763x over previous
#include <cuda_runtime.h>
#include <math.h>

// B = H = IN = 256, c = 1. Dead code (Wh*/Uh*, r_point_h) skipped.

#define NB 256
#define MAXN 0.996f          // (1 - 4e-3)/sqrt(c)
#define EPSN 1e-15f
#define CLIPV 0.9999999f     // 1 - 1e-7 in f32

// ---------------- scratch ---------------------------------------------------
__device__ float g_w[4][NB * NB];     // w = sinh(mlr logits) per fc, [b][cl]
__device__ float g_scale[4][NB];      // sqrt(row-sumsq of w)+1
__device__ float g_nz[4][NB];         // ||z_cl||
__device__ float g_coef[4][NB];       // 2*||z_cl||/cosh(r_cl)^2
__device__ float g_y2[2][NB];         // ||x_b||^2 : [0]=hidden, [1]=hyp_x

// ---------------- fast math helpers -----------------------------------------
__device__ __forceinline__ float fsqrt_(float x) { float r; asm("sqrt.approx.f32 %0,%1;" : "=f"(r) : "f"(x)); return r; }
__device__ __forceinline__ float frcp_(float x)  { float r; asm("rcp.approx.f32 %0,%1;"  : "=f"(r) : "f"(x)); return r; }
__device__ __forceinline__ float ftanh_(float x) { float e = __expf(2.0f * x); return 1.0f - 2.0f * frcp_(e + 1.0f); }
__device__ __forceinline__ float fatanh_(float x){ return 0.5f * __logf((1.0f + x) * frcp_(1.0f - x)); }
__device__ __forceinline__ float fasinh_(float x){ float a = fabsf(x); float l = __logf(a + fsqrt_(fmaf(a, a, 1.0f))); return copysignf(l, x); }
__device__ __forceinline__ float fsinh_(float x) { float e = __expf(x); return 0.5f * (e - frcp_(e)); }
__device__ __forceinline__ float fsigm_(float x) { return frcp_(1.0f + __expf(-x)); }

__device__ __forceinline__ float wsum8(float v) {
    #pragma unroll
    for (int o = 16; o; o >>= 1) v += __shfl_xor_sync(0xffffffffu, v, o);
    return v;
}

// ---------------- K0: per-row stats (warp per row) ---------------------------
__global__ void k0_stats(const float* __restrict__ Wz_z, const float* __restrict__ Wz_r,
                         const float* __restrict__ Uz_z, const float* __restrict__ Uz_r,
                         const float* __restrict__ Wr_z, const float* __restrict__ Wr_r,
                         const float* __restrict__ Ur_z, const float* __restrict__ Ur_r,
                         const float* __restrict__ hidden, const float* __restrict__ hyp_x)
{
    const int gw = (blockIdx.x * blockDim.x + threadIdx.x) >> 5;
    const int lane = threadIdx.x & 31;
    const int m = gw >> 8, row = gw & 255;
    const float* p;
    if      (m == 0) p = Wz_z;
    else if (m == 1) p = Uz_z;
    else if (m == 2) p = Wr_z;
    else if (m == 3) p = Ur_z;
    else if (m == 4) p = hidden;
    else             p = hyp_x;

    const float4* p4 = reinterpret_cast<const float4*>(p + row * NB);
    float4 v0 = p4[lane], v1 = p4[lane + 32];
    float s = v0.x*v0.x + v0.y*v0.y + v0.z*v0.z + v0.w*v0.w
            + v1.x*v1.x + v1.y*v1.y + v1.z*v1.z + v1.w*v1.w;
    s = wsum8(s);
    if (lane == 0) {
        if (m < 4) {
            const float* R;
            if      (m == 0) R = Wz_r;
            else if (m == 1) R = Uz_r;
            else if (m == 2) R = Wr_r;
            else             R = Ur_r;
            float nz = sqrtf(s);
            g_nz[m][row] = nz;
            float ch = coshf(R[row]);
            g_coef[m][row] = 2.0f * nz / (ch * ch);
        } else {
            g_y2[m - 4][row] = s;
        }
    }
}

// ---------------- mlr/sinh epilogue ------------------------------------------
__device__ __forceinline__ float fc_elem(int fc, int cl, float rb, float y2b, float g)
{
    const float nz = g_nz[fc][cl];
    const float s  = g * frcp_(nz);
    float alpha = ftanh_(rb * nz);
    float aa = fabsf(alpha);
    if (aa > MAXN) alpha *= MAXN * frcp_(aa);
    const float x2 = alpha * alpha;
    const float xy = -alpha * s;
    const float A  = 1.0f + 2.0f * xy + y2b;
    const float Bc = 1.0f - x2;
    const float den = fmaxf(1.0f + 2.0f * xy + x2 * y2b, EPSN);
    const float inv = frcp_(den);
    float pa = (Bc * s - A * alpha) * inv;
    float p2 = (A * A * x2 - 2.0f * A * Bc * alpha * s + Bc * Bc * y2b) * (inv * inv);
    float pn = fmaxf(fsqrt_(fmaxf(p2, 0.0f)), EPSN);
    if (pn > MAXN) { float f = MAXN * frcp_(pn); pa *= f; p2 *= f * f; }
    const float lam = 2.0f * frcp_(1.0f - p2);
    return fsinh_(g_coef[fc][cl] * fasinh_(pa * lam));
}

// ---------------- K1: 4 GEMMs, 64x32 tile, 4x2 microtile, 256 threads --------
// grid (8 n-tiles, 4 m-tiles, 4 fc) = 128 blocks -> one wave, 8 warps/block.
__global__ void __launch_bounds__(256) k1_gemm(
    const float* __restrict__ hidden, const float* __restrict__ hyp_x,
    const float* __restrict__ Wz_z, const float* __restrict__ Wz_r,
    const float* __restrict__ Uz_z, const float* __restrict__ Uz_r,
    const float* __restrict__ Wr_z, const float* __restrict__ Wr_r,
    const float* __restrict__ Ur_z, const float* __restrict__ Ur_r)
{
    const int fc = blockIdx.z;
    const float *X, *Z, *R;
    int ysel;
    if      (fc == 0) { X = hidden; Z = Wz_z; R = Wz_r; ysel = 0; }
    else if (fc == 1) { X = hyp_x;  Z = Uz_z; R = Uz_r; ysel = 1; }
    else if (fc == 2) { X = hidden; Z = Wr_z; R = Wr_r; ysel = 0; }
    else              { X = hyp_x;  Z = Ur_z; R = Ur_r; ysel = 1; }

    __shared__ float4 Xs[64][17];   // 64 m-rows x 64 k
    __shared__ float4 Zs[32][17];   // 32 n-rows x 64 k

    const int b0 = blockIdx.y * 64, c0 = blockIdx.x * 32;
    const int tid = threadIdx.x;
    const int tx = tid & 15, ty = tid >> 4;   // 16 x 16 thread grid

    float a00=0.f,a01=0.f,a10=0.f,a11=0.f,a20=0.f,a21=0.f,a30=0.f,a31=0.f;

    for (int kc = 0; kc < 256; kc += 64) {
        #pragma unroll
        for (int i = tid; i < 1024; i += 256) {
            const int r = i >> 4, c = i & 15;
            Xs[r][c] = reinterpret_cast<const float4*>(X + (b0 + r) * 256 + kc)[c];
        }
        #pragma unroll
        for (int i = tid; i < 512; i += 256) {
            const int r = i >> 4, c = i & 15;
            Zs[r][c] = reinterpret_cast<const float4*>(Z + (c0 + r) * 256 + kc)[c];
        }
        __syncthreads();
        #pragma unroll
        for (int q = 0; q < 16; q++) {
            const float4 x0 = Xs[ty][q],      x1 = Xs[ty + 16][q];
            const float4 x2 = Xs[ty + 32][q], x3 = Xs[ty + 48][q];
            const float4 z0 = Zs[tx][q],      z1 = Zs[tx + 16][q];
            a00 = fmaf(x0.x, z0.x, a00); a00 = fmaf(x0.y, z0.y, a00);
            a00 = fmaf(x0.z, z0.z, a00); a00 = fmaf(x0.w, z0.w, a00);
            a01 = fmaf(x0.x, z1.x, a01); a01 = fmaf(x0.y, z1.y, a01);
            a01 = fmaf(x0.z, z1.z, a01); a01 = fmaf(x0.w, z1.w, a01);
            a10 = fmaf(x1.x, z0.x, a10); a10 = fmaf(x1.y, z0.y, a10);
            a10 = fmaf(x1.z, z0.z, a10); a10 = fmaf(x1.w, z0.w, a10);
            a11 = fmaf(x1.x, z1.x, a11); a11 = fmaf(x1.y, z1.y, a11);
            a11 = fmaf(x1.z, z1.z, a11); a11 = fmaf(x1.w, z1.w, a11);
            a20 = fmaf(x2.x, z0.x, a20); a20 = fmaf(x2.y, z0.y, a20);
            a20 = fmaf(x2.z, z0.z, a20); a20 = fmaf(x2.w, z0.w, a20);
            a21 = fmaf(x2.x, z1.x, a21); a21 = fmaf(x2.y, z1.y, a21);
            a21 = fmaf(x2.z, z1.z, a21); a21 = fmaf(x2.w, z1.w, a21);
            a30 = fmaf(x3.x, z0.x, a30); a30 = fmaf(x3.y, z0.y, a30);
            a30 = fmaf(x3.z, z0.z, a30); a30 = fmaf(x3.w, z0.w, a30);
            a31 = fmaf(x3.x, z1.x, a31); a31 = fmaf(x3.y, z1.y, a31);
            a31 = fmaf(x3.z, z1.z, a31); a31 = fmaf(x3.w, z1.w, a31);
        }
        __syncthreads();
    }

    // epilogue: m = b0 + ty + 16i (i<4), n = c0 + tx + 16j (j<2)
    const int cA = c0 + tx, cB = c0 + tx + 16;
    float accs[4][2] = {{a00,a01},{a10,a11},{a20,a21},{a30,a31}};
    #pragma unroll
    for (int i = 0; i < 4; i++) {
        const int m = b0 + ty + 16 * i;
        const float rb = R[m];
        const float y2 = g_y2[ysel][m];
        g_w[fc][m * 256 + cA] = fc_elem(fc, cA, rb, y2, accs[i][0]);
        g_w[fc][m * 256 + cB] = fc_elem(fc, cB, rb, y2, accs[i][1]);
    }
}

// ---------------- K1b: per-row scale (warp per row, float4 loads) ------------
__global__ void k1b_scale()
{
    const int gw = (blockIdx.x * blockDim.x + threadIdx.x) >> 5;
    const int lane = threadIdx.x & 31;
    const int fc = gw >> 8, row = gw & 255;
    const float4* p4 = reinterpret_cast<const float4*>(&g_w[fc][row * NB]);
    float4 v0 = p4[lane], v1 = p4[lane + 32];
    float s = v0.x*v0.x + v0.y*v0.y + v0.z*v0.z + v0.w*v0.w
            + v1.x*v1.x + v1.y*v1.y + v1.z*v1.z + v1.w*v1.w;
    s = wsum8(s);
    if (lane == 0) g_scale[fc][row] = sqrtf(s) + 1.0f;
}

// ---------------- batched per-half block reduction (256-thread halves) -------
// sm: this half's region of 15*8 floats; ltid: 0..255 within the half.
template<int K>
__device__ __forceinline__ void bred2(float* v, float* sm, int ltid)
{
    const int lane = ltid & 31, wid = ltid >> 5;
    __syncthreads();     // protect sm from previous round's readers (both halves)
    #pragma unroll
    for (int k = 0; k < K; k++) {
        float x = v[k];
        #pragma unroll
        for (int o = 16; o; o >>= 1) x += __shfl_xor_sync(0xffffffffu, x, o);
        if (lane == 0) sm[k * 8 + wid] = x;
    }
    __syncthreads();
    if (ltid < K) {
        float s = sm[ltid * 8];
        #pragma unroll
        for (int w = 1; w < 8; w++) s += sm[ltid * 8 + w];
        sm[ltid * 8] = s;
    }
    __syncthreads();
    #pragma unroll
    for (int k = 0; k < K; k++) v[k] = sm[k * 8];
}

// ---------------- madd scalar helper -----------------------------------------
struct MS { float A, B, inv, m, nc; };
__device__ __forceinline__ MS madds(float sxx, float syy, float sxy)
{
    MS r;
    r.A = 1.0f + 2.0f * sxy + syy;
    r.B = 1.0f - sxx;
    float den = fmaxf(1.0f + 2.0f * sxy + sxx * syy, EPSN);
    r.inv = frcp_(den);
    float n2 = (r.A * r.A * sxx + 2.0f * r.A * r.B * sxy + r.B * r.B * syy) * r.inv * r.inv;
    float n = fmaxf(fsqrt_(fmaxf(n2, 0.0f)), EPSN);
    r.m = (n > MAXN) ? MAXN * frcp_(n) : 1.0f;
    r.nc = fminf(n, MAXN);
    return r;
}

// ---------------- K2: 2 rows per 512-thread block -> grid 128 = one wave -----
__global__ void __launch_bounds__(512) k2_final(
    const float* __restrict__ hidden, const float* __restrict__ bz,
    const float* __restrict__ br, const float* __restrict__ bh,
    float* __restrict__ out)
{
    __shared__ float smbuf[2][15 * 8];
    const int half = threadIdx.x >> 8;          // 0 or 1
    const int ltid = threadIdx.x & 255;
    const int b = blockIdx.x * 2 + half;
    const int j = ltid;
    float* sm = smbuf[half];

    const float hid = hidden[b * NB + j];
    const float bhv = bh[j], bzv = bz[j], brv = br[j];
    const float F0 = g_scale[0][j] * g_w[0][b * NB + j];
    const float G0 = g_scale[1][j] * g_w[1][b * NB + j];
    const float F1 = g_scale[2][j] * g_w[2][b * NB + j];
    const float G1 = g_scale[3][j] * g_w[3][b * NB + j];

    // ---- round 1: 15 sums ----
    float v[15];
    v[0] = F0 * F0;  v[1] = G0 * G0;  v[2] = F0 * G0;
    v[3] = F0 * bzv; v[4] = G0 * bzv; v[5] = bzv * bzv;
    v[6] = F1 * F1;  v[7] = G1 * G1;  v[8] = F1 * G1;
    v[9] = F1 * brv; v[10] = G1 * brv; v[11] = brv * brv;
    v[12] = hid * hid; v[13] = bhv * bhv; v[14] = hid * bhv;
    bred2<15>(v, sm, ltid);
    const float sFF0 = v[0], sGG0 = v[1], sFG0 = v[2], sFb0 = v[3], sGb0 = v[4], sbb0 = v[5];
    const float sFF1 = v[6], sGG1 = v[7], sFG1 = v[8], sFb1 = v[9], sGb1 = v[10], sbb1 = v[11];
    const float shh = v[12], sbhbh = v[13], shbh = v[14];

    // ---- z gate (closed form) ----
    MS z1 = madds(sFF0, sGG0, sFG0);
    float zcF = z1.m * z1.inv * z1.A, zcG = z1.m * z1.inv * z1.B;
    MS z2 = madds(z1.nc * z1.nc, sbb0, zcF * sFb0 + zcG * sGb0);
    float k2a = z2.m * z2.inv * z2.A, k2b = z2.m * z2.inv * z2.B;
    float facz = fatanh_(z2.nc) * frcp_(z2.nc);
    const float zg = fsigm_(facz * (k2a * (zcF * F0 + zcG * G0) + k2b * bzv));

    // ---- r gate ----
    MS r1 = madds(sFF1, sGG1, sFG1);
    float rcF = r1.m * r1.inv * r1.A, rcG = r1.m * r1.inv * r1.B;
    MS r2 = madds(r1.nc * r1.nc, sbb1, rcF * sFb1 + rcG * sGb1);
    float l2a = r2.m * r2.inv * r2.A, l2b = r2.m * r2.inv * r2.B;
    float facr = fatanh_(r2.nc) * frcp_(r2.nc);
    const float rg = fsigm_(facr * (l2a * (rcF * F1 + rcG * G1) + l2b * brv));

    // ---- round 2: 4 sums ----
    float v2[4];
    v2[0] = rg * rg; v2[1] = rg * bhv; v2[2] = hid * rg; v2[3] = zg * zg;
    bred2<4>(v2, sm, ltid);
    const float srr = v2[0], srbh = v2[1], shr = v2[2], szz = v2[3];

    // ---- h_tilde = madd(rg, bh); mh = madd(-hid, ht) ----
    MS h3 = madds(srr, sbhbh, srbh);
    float hA = h3.m * h3.inv * h3.A, hB = h3.m * h3.inv * h3.B;
    float sht_h = hA * shr + hB * shbh;
    MS h4 = madds(shh, h3.nc * h3.nc, -sht_h);
    float mA = -h4.m * h4.inv * h4.A;
    float mR =  h4.m * h4.inv * h4.B * hA;
    float mB =  h4.m * h4.inv * h4.B * hB;

    // ---- round 3: 2 sums ----
    const float wx = (mA * hid + mR * rg + mB * bhv) * zg;
    float v3[2];
    v3[0] = wx * wx; v3[1] = hid * wx;
    bred2<2>(v3, sm, ltid);
    const float swx = v3[0], shwx = v3[1];

    // ---- mobius pointwise mul + final add (closed form) ----
    float xn  = fmaxf(fsqrt_(szz), EPSN);
    float wxn = fmaxf(fsqrt_(swx), EPSN);
    float tt  = fatanh_(fminf(xn, CLIPV));
    float f   = ftanh_(wxn * frcp_(xn) * tt);
    float pn  = fmaxf(f, EPSN);
    float cf  = f * frcp_(wxn);
    if (pn > MAXN) cf *= MAXN * frcp_(pn);
    float pnc = fminf(pn, MAXN);

    MS o5 = madds(shh, pnc * pnc, cf * shwx);
    float oH = o5.m * o5.inv * o5.A, oP = o5.m * o5.inv * o5.B * cf;

    out[b * NB + j] = oH * hid + oP * wx;
}

// ---------------- launch ------------------------------------------------------
extern "C" void kernel_launch(void* const* d_in, const int* in_sizes, int n_in,
                              void* d_out, int out_size)
{
    const float* hyp_x  = (const float*)d_in[0];
    const float* hidden = (const float*)d_in[1];
    const float* Wz_z   = (const float*)d_in[2];
    const float* Wz_r   = (const float*)d_in[3];
    const float* Uz_z   = (const float*)d_in[4];
    const float* Uz_r   = (const float*)d_in[5];
    const float* Wr_z   = (const float*)d_in[6];
    const float* Wr_r   = (const float*)d_in[7];
    const float* Ur_z   = (const float*)d_in[8];
    const float* Ur_r   = (const float*)d_in[9];
    const float* b_z    = (const float*)d_in[14];
    const float* b_r    = (const float*)d_in[15];
    const float* b_h    = (const float*)d_in[16];
    float* out = (float*)d_out;

    k0_stats<<<192, 256>>>(Wz_z, Wz_r, Uz_z, Uz_r, Wr_z, Wr_r, Ur_z, Ur_r, hidden, hyp_x);
    k1_gemm<<<dim3(8, 4, 4), 256>>>(hidden, hyp_x, Wz_z, Wz_r, Uz_z, Uz_r,
                                    Wr_z, Wr_r, Ur_z, Ur_r);
    k1b_scale<<<128, 256>>>();
    k2_final<<<128, 512>>>(hidden, b_z, b_r, b_h, out);
}